// round 15
// baseline (speedup 1.0000x reference)
#include <cuda_runtime.h>
#include <cuda_fp16.h>
#include <cstdint>
#include <math.h>

#define EMBED   1024
#define NHEADS  16
#define MAXROWS 4096                    // B*S
#define NELEM   (MAXROWS * EMBED)       // 4M
#define WELEM   (EMBED * EMBED)         // 1M
#define QSCALE  0.18033688011112042f    // (1/8) * log2(e)

// Scratch (no cudaMalloc allowed).
__device__ __half g_xq[NELEM];          // fp16 query input
__device__ __half g_xk[NELEM];          // fp16 key input
__device__ __half g_xv[NELEM];          // fp16 value input
__device__ __half g_wh[4 * WELEM];      // fp16 Wq|Wk|Wv|Wo
__device__ __half g_qh[NELEM];          // fp16 q (scaled by QSCALE)
__device__ __half g_kh[NELEM];          // fp16 k
__device__ __half g_vh[NELEM];          // fp16 v
__device__ __half g_ch[NELEM];          // fp16 ctx

// ============================ helpers ======================================
__device__ __forceinline__ uint32_t smem_u32(const void* p) {
    uint32_t a;
    asm("{ .reg .u64 t; cvta.to.shared.u64 t, %1; cvt.u32.u64 %0, t; }"
        : "=r"(a) : "l"(p));
    return a;
}
__device__ __forceinline__ uint32_t packh2(float lo, float hi) {
    __half2 h = __floats2half2_rn(lo, hi);
    return *(uint32_t*)&h;
}
__device__ __forceinline__ float ex2f(float x) {   // MUFU 2^x (fp32)
    float y;
    asm("ex2.approx.f32 %0, %1;" : "=f"(y) : "f"(x));
    return y;
}
__device__ __forceinline__ uint32_t hexp2x2(uint32_t x) {  // MUFU 2^x on half2
    uint32_t y;
    asm("ex2.approx.f16x2 %0, %1;" : "=r"(y) : "r"(x));
    return y;
}

#define CPA(dst, src) \
    asm volatile("cp.async.cg.shared.global [%0], [%1], 16;" :: "r"(dst), "l"(src) : "memory")
#define CP_COMMIT() asm volatile("cp.async.commit_group;" ::: "memory")
#define CP_WAIT1()  asm volatile("cp.async.wait_group 1;" ::: "memory")
#define CP_WAIT0()  asm volatile("cp.async.wait_group 0;" ::: "memory")

// m16n8k16 fp16 MMA, fp32 accumulate in place.
__device__ __forceinline__ void mma16(float* d, const uint32_t* a, uint32_t b0, uint32_t b1) {
    asm volatile(
        "mma.sync.aligned.m16n8k16.row.col.f32.f16.f16.f32 "
        "{%0,%1,%2,%3},{%4,%5,%6,%7},{%8,%9},{%0,%1,%2,%3};"
        : "+f"(d[0]), "+f"(d[1]), "+f"(d[2]), "+f"(d[3])
        : "r"(a[0]), "r"(a[1]), "r"(a[2]), "r"(a[3]), "r"(b0), "r"(b1));
}
__device__ __forceinline__ void ldsm_x4(uint32_t* r, uint32_t addr) {
    asm volatile("ldmatrix.sync.aligned.m8n8.x4.shared.b16 {%0,%1,%2,%3}, [%4];"
                 : "=r"(r[0]), "=r"(r[1]), "=r"(r[2]), "=r"(r[3]) : "r"(addr));
}
__device__ __forceinline__ void ldsm_x4t(uint32_t* r, uint32_t addr) {
    asm volatile("ldmatrix.sync.aligned.m8n8.x4.trans.shared.b16 {%0,%1,%2,%3}, [%4];"
                 : "=r"(r[0]), "=r"(r[1]), "=r"(r[2]), "=r"(r[3]) : "r"(addr));
}

// ===========================================================================
// Prep: fp32 -> fp16, 16 elements/thread. blockIdx.y selects one of 7 tensors.
// ===========================================================================
__global__ __launch_bounds__(256) void cvt7(
    const float* __restrict__ s0, const float* __restrict__ s1,
    const float* __restrict__ s2, const float* __restrict__ s3,
    const float* __restrict__ s4, const float* __restrict__ s5,
    const float* __restrict__ s6,
    __half* __restrict__ d0, __half* __restrict__ d1, __half* __restrict__ d2,
    __half* __restrict__ d3, __half* __restrict__ d4, __half* __restrict__ d5,
    __half* __restrict__ d6, int n_big, int n_small)
{
    const int z = blockIdx.y;
    const float* s; __half* d; int n;
    switch (z) {
        case 0: s = s0; d = d0; n = n_big;   break;
        case 1: s = s1; d = d1; n = n_big;   break;
        case 2: s = s2; d = d2; n = n_big;   break;
        case 3: s = s3; d = d3; n = n_small; break;
        case 4: s = s4; d = d4; n = n_small; break;
        case 5: s = s5; d = d5; n = n_small; break;
        default: s = s6; d = d6; n = n_small; break;
    }
    int i = (blockIdx.x * 256 + threadIdx.x) * 16;
    if (i < n) {
        float4 a = *(const float4*)(s + i);
        float4 b = *(const float4*)(s + i + 4);
        float4 c = *(const float4*)(s + i + 8);
        float4 e = *(const float4*)(s + i + 12);
        uint4 o1, o2;
        o1.x = packh2(a.x, a.y);
        o1.y = packh2(a.z, a.w);
        o1.z = packh2(b.x, b.y);
        o1.w = packh2(b.z, b.w);
        o2.x = packh2(c.x, c.y);
        o2.y = packh2(c.z, c.w);
        o2.z = packh2(e.x, e.y);
        o2.w = packh2(e.z, e.w);
        *(uint4*)(d + i)     = o1;
        *(uint4*)(d + i + 8) = o2;
    }
}

// ===========================================================================
// Persistent fp16 tensor-core NT GEMM: C = A W^T + bias.
// Grid of P CTAs; CTA cid statically owns tiles {cid, cid+P, cid+2P, ...} of
// ntile_total. Tile T: z = T>>8, bm = (T&31)*128, bn = ((T>>5)&7)*128.
// The 3-stage cp.async ring runs CONTINUOUSLY across tile boundaries through
// one flat (tile x chunk) loop: while tile t's epilogue runs, chunks 0-1 of
// tile t+1 are already in flight. Inner pipeline/fragments/epilogue math are
// instruction-identical to the validated champion.
// mode 1: fp16 out (z0 scaled by QSCALE). mode 0: fp32 out.
// ===========================================================================
#define G_SMEM_BYTES 98304   // 3 stages x (A 16KB + W 16KB)

__global__ __launch_bounds__(256, 2) void gemm_p(
    const __half* __restrict__ A0, const __half* __restrict__ A1, const __half* __restrict__ A2,
    const __half* __restrict__ W0, const __half* __restrict__ W1, const __half* __restrict__ W2,
    const float* __restrict__ b0, const float* __restrict__ b1, const float* __restrict__ b2,
    float* __restrict__ Cf, __half* __restrict__ H0, __half* __restrict__ H1,
    __half* __restrict__ H2, int N, int K, int ntile_total, int mode)
{
    extern __shared__ __align__(16) char smem[];
    const uint32_t sb = smem_u32(smem);

    const int cid  = blockIdx.x;
    const int tid  = threadIdx.x;
    const int lane = tid & 31;
    const int wid  = tid >> 5;
    const int g    = lane >> 2;
    const int tig  = lane & 3;
    const int wm   = wid & 1;
    const int wn   = wid >> 1;

    int tiles[3];
    int ntl = 0;
    for (int T = cid; T < ntile_total && ntl < 3; T += gridDim.x) tiles[ntl++] = T;
    if (ntl == 0) return;
    const int total_q = ntl << 4;    // 16 chunks per tile

    const int lrow = tid >> 3;       // 0..31
    const int lc8  = tid & 7;        // 16B chunk 0..7

    // Issue chunk gq (global) into ring stage st.
    auto issue = [&](int gq, int st) {
        const int T  = tiles[gq >> 4];
        const int c  = gq & 15;
        const int z  = T >> 8;
        const int bm = (T & 31) << 7;
        const int bn = ((T >> 5) & 7) << 7;
        const __half* A = (z == 0) ? A0 : (z == 1) ? A1 : A2;
        const __half* W = (z == 0) ? W0 : (z == 1) ? W1 : W2;
        const int k0 = c * 64;
        #pragma unroll
        for (int p = 0; p < 4; p++) {
            int r = lrow + p * 32;
            uint32_t dA = sb + st * 32768u + (uint32_t)(r * 128 + ((lc8 ^ (r & 7)) << 4));
            CPA(dA,          A + (size_t)(bm + r) * K + k0 + lc8 * 8);
            CPA(dA + 16384u, W + (size_t)(bn + r) * K + k0 + lc8 * 8);
        }
    };

    float acc[4][4][4];
    #pragma unroll
    for (int mt = 0; mt < 4; mt++)
        #pragma unroll
        for (int nt = 0; nt < 4; nt++)
            #pragma unroll
            for (int r = 0; r < 4; r++) acc[mt][nt][r] = 0.f;

    issue(0, 0); CP_COMMIT();
    issue(1, 1); CP_COMMIT();

    const int l7  = lane & 7;
    const int l8  = (lane >> 3) & 1;
    const int l16 = lane >> 4;

    int st_c  = 0;   // stage of chunk gq
    int st_n2 = 2;   // stage for chunk gq+2

    for (int gq = 0; gq < total_q; gq++) {
        if (gq + 1 < total_q) CP_WAIT1(); else CP_WAIT0();
        __syncthreads();
        if (gq + 2 < total_q) { issue(gq + 2, st_n2); CP_COMMIT(); }

        const uint32_t stg = sb + (uint32_t)(st_c * 32768);

        #pragma unroll
        for (int kk = 0; kk < 4; kk++) {
            uint32_t af[4][4], bf[4][2];
            #pragma unroll
            for (int mt = 0; mt < 4; mt++) {
                int row = wm * 64 + mt * 16 + l8 * 8 + l7;
                int c8  = kk * 2 + l16;
                ldsm_x4(af[mt], stg + (uint32_t)(row * 128 + ((c8 ^ (row & 7)) << 4)));
            }
            #pragma unroll
            for (int ntp = 0; ntp < 2; ntp++) {
                int row = wn * 32 + ntp * 16 + l16 * 8 + l7;
                int c8  = kk * 2 + l8;
                uint32_t r4[4];
                ldsm_x4(r4, stg + 16384u + (uint32_t)(row * 128 + ((c8 ^ (row & 7)) << 4)));
                bf[2 * ntp][0]     = r4[0];
                bf[2 * ntp][1]     = r4[1];
                bf[2 * ntp + 1][0] = r4[2];
                bf[2 * ntp + 1][1] = r4[3];
            }
            #pragma unroll
            for (int mt = 0; mt < 4; mt++)
                #pragma unroll
                for (int nt = 0; nt < 4; nt++)
                    mma16(acc[mt][nt], af[mt], bf[nt][0], bf[nt][1]);
        }
        st_c  = (st_c  == 2) ? 0 : st_c + 1;
        st_n2 = (st_n2 == 2) ? 0 : st_n2 + 1;

        // Tile finished: epilogue (registers/global only — overlaps with the
        // in-flight cp.asyncs for the next tile's first chunks).
        if ((gq & 15) == 15) {
            const int T  = tiles[gq >> 4];
            const int z  = T >> 8;
            const int bm = (T & 31) << 7;
            const int bn = ((T >> 5) & 7) << 7;
            const float* bias = (z == 0) ? b0 : (z == 1) ? b1 : b2;

            if (mode == 1) {
                __half* H = (z == 0) ? H0 : (z == 1) ? H1 : H2;
                const float sc = (z == 0) ? QSCALE : 1.f;
                #pragma unroll
                for (int nt = 0; nt < 4; nt++) {
                    int col = bn + wn * 32 + nt * 8 + tig * 2;
                    float2 bv = *(const float2*)(bias + col);
                    #pragma unroll
                    for (int mt = 0; mt < 4; mt++) {
                        int r0 = bm + wm * 64 + mt * 16 + g;
                        *(uint32_t*)(H + (size_t)r0 * N + col) =
                            packh2((acc[mt][nt][0] + bv.x) * sc, (acc[mt][nt][1] + bv.y) * sc);
                        *(uint32_t*)(H + (size_t)(r0 + 8) * N + col) =
                            packh2((acc[mt][nt][2] + bv.x) * sc, (acc[mt][nt][3] + bv.y) * sc);
                    }
                }
            } else {
                #pragma unroll
                for (int nt = 0; nt < 4; nt++) {
                    int col = bn + wn * 32 + nt * 8 + tig * 2;
                    float2 bv = *(const float2*)(bias + col);
                    #pragma unroll
                    for (int mt = 0; mt < 4; mt++) {
                        int r0 = bm + wm * 64 + mt * 16 + g;
                        *(float2*)(Cf + (size_t)r0 * N + col) =
                            make_float2(acc[mt][nt][0] + bv.x, acc[mt][nt][1] + bv.y);
                        *(float2*)(Cf + (size_t)(r0 + 8) * N + col) =
                            make_float2(acc[mt][nt][2] + bv.x, acc[mt][nt][3] + bv.y);
                    }
                }
            }
            #pragma unroll
            for (int mt = 0; mt < 4; mt++)
                #pragma unroll
                for (int nt = 0; nt < 4; nt++)
                    #pragma unroll
                    for (int r = 0; r < 4; r++) acc[mt][nt][r] = 0.f;
        }
    }
}

// ===========================================================================
// fp16 tensor-core flash attention — exact R13 champion configuration.
// ===========================================================================
#define HPAD 72
#define OFF_Q  0
#define KV_STG (2 * 64 * HPAD)                   // halves per K+V stage
#define OFF_K(s) (128 * HPAD + (s) * KV_STG)
#define OFF_V(s) (OFF_K(s) + 64 * HPAD)
#define FLASH_SMEM ((128 * HPAD + 4 * KV_STG) * 2)   // 92160 B

__global__ __launch_bounds__(256, 2) void flash_tc(
    const __half* __restrict__ Qh, const __half* __restrict__ Kh,
    const __half* __restrict__ Vh, __half* __restrict__ ctx, int S)
{
    extern __shared__ __half smh[];
    const uint32_t sb = smem_u32(smh);

    const int tid  = threadIdx.x;
    const int lane = tid & 31;
    const int warp = tid >> 5;
    const int g    = lane >> 2;
    const int tig  = lane & 3;
    const int s0   = blockIdx.x * 128;
    const int h    = blockIdx.y;
    const int b    = blockIdx.z;
    const size_t base = ((size_t)b * S) * EMBED + (size_t)h * 64;

    const int frow = tid >> 3;
    const int fc8  = tid & 7;

    auto issueKV = [&](int c0, int st) {
        const uint32_t kOff = (uint32_t)OFF_K(st);
        const uint32_t vOff = (uint32_t)OFF_V(st);
        #pragma unroll
        for (int i = 0; i < 2; i++) {
            int row = frow + i * 32;
            uint32_t d = (uint32_t)(row * HPAD + fc8 * 8) * 2u;
            const size_t src = base + (size_t)(c0 + row) * EMBED + fc8 * 8;
            CPA(sb + kOff * 2u + d, Kh + src);
            CPA(sb + vOff * 2u + d, Vh + src);
        }
    };
    auto issuePair = [&](int p, int slot) {
        issueKV(p * 128,      slot * 2);
        issueKV(p * 128 + 64, slot * 2 + 1);
    };

    // Prologue: Q + pair 0 as one cp.async group.
    #pragma unroll
    for (int i = 0; i < 4; i++) {
        int row = frow + i * 32;
        CPA(sb + (uint32_t)(OFF_Q + row * HPAD + fc8 * 8) * 2u,
            Qh + base + (size_t)(s0 + row) * EMBED + fc8 * 8);
    }
    issuePair(0, 0);
    CP_COMMIT();

    CP_WAIT0();
    __syncthreads();

    const int l7  = lane & 7;
    const int l8  = (lane >> 3) & 1;
    const int l16 = lane >> 4;

    // Q A-fragments (persist in registers).
    uint32_t qa[4][4];
    {
        int qr = warp * 16 + l8 * 8 + l7;
        #pragma unroll
        for (int kk = 0; kk < 4; kk++)
            ldsm_x4(qa[kk], sb + (uint32_t)((OFF_Q + qr * HPAD + kk * 16 + l16 * 8) * 2));
    }

    // Constant B-fragment for the ones-column row-sum mma.
    const uint32_t bone = (lane < 4) ? 0x3C003C00u : 0u;

    float o[9][4] = {};   // o[8] = row-sum accumulator
    float m0 = -1e30f, m1 = -1e30f;

    const int NP = S >> 7;   // 16 tile-pairs
    for (int p = 0; p < NP; p++) {
        if (p > 0) {
            CP_WAIT0();
            __syncthreads();
        }
        if (p + 1 < NP) { issuePair(p + 1, (p + 1) & 1); CP_COMMIT(); }

        #pragma unroll
        for (int u = 0; u < 2; u++) {
            const int st = (p & 1) * 2 + u;
            const uint32_t kbase = sb + (uint32_t)(OFF_K(st) * 2);
            const uint32_t vbase = sb + (uint32_t)(OFF_V(st) * 2);

            // ---- S = Q' K^T (log2-units) ----
            float c[8][4];
            #pragma unroll
            for (int j = 0; j < 8; j++)
                #pragma unroll
                for (int r = 0; r < 4; r++) c[j][r] = 0.f;

            #pragma unroll
            for (int kk = 0; kk < 4; kk++) {
                #pragma unroll
                for (int jp = 0; jp < 4; jp++) {
                    uint32_t r4[4];
                    uint32_t addr = kbase + (uint32_t)((((2 * jp + l16) * 8 + l7) * HPAD
                                     + kk * 16 + l8 * 8) * 2);
                    ldsm_x4(r4, addr);
                    mma16(c[2 * jp],     qa[kk], r4[0], r4[1]);
                    mma16(c[2 * jp + 1], qa[kk], r4[2], r4[3]);
                }
            }

            // ---- online softmax (rows g and g+8) ----
            float mx0 = -1e30f, mx1 = -1e30f;
            #pragma unroll
            for (int j = 0; j < 8; j++) {
                mx0 = fmaxf(mx0, fmaxf(c[j][0], c[j][1]));
                mx1 = fmaxf(mx1, fmaxf(c[j][2], c[j][3]));
            }
            mx0 = fmaxf(mx0, __shfl_xor_sync(0xffffffffu, mx0, 1));
            mx0 = fmaxf(mx0, __shfl_xor_sync(0xffffffffu, mx0, 2));
            mx1 = fmaxf(mx1, __shfl_xor_sync(0xffffffffu, mx1, 1));
            mx1 = fmaxf(mx1, __shfl_xor_sync(0xffffffffu, mx1, 2));

            bool grew = (mx0 > m0) || (mx1 > m1);
            float mn0 = fmaxf(m0, mx0), mn1 = fmaxf(m1, mx1);
            if (__any_sync(0xffffffffu, grew)) {
                float a0 = ex2f(m0 - mn0), a1 = ex2f(m1 - mn1);
                #pragma unroll
                for (int dj = 0; dj < 9; dj++) {
                    o[dj][0] *= a0; o[dj][1] *= a0;
                    o[dj][2] *= a1; o[dj][3] *= a1;
                }
            }
            m0 = mn0; m1 = mn1;

            // P fragments: packed fp16 exp straight into A-frag layout.
            uint32_t pa[4][4];
            #pragma unroll
            for (int kk = 0; kk < 4; kk++) {
                pa[kk][0] = hexp2x2(packh2(c[2 * kk][0] - mn0,     c[2 * kk][1] - mn0));
                pa[kk][1] = hexp2x2(packh2(c[2 * kk][2] - mn1,     c[2 * kk][3] - mn1));
                pa[kk][2] = hexp2x2(packh2(c[2 * kk + 1][0] - mn0, c[2 * kk + 1][1] - mn0));
                pa[kk][3] = hexp2x2(packh2(c[2 * kk + 1][2] - mn1, c[2 * kk + 1][3] - mn1));
            }

            // ---- O += P V (o[8] = row sums via constant ones-column) ----
            #pragma unroll
            for (int kk = 0; kk < 4; kk++) {
                uint32_t rowa = (uint32_t)((kk * 16 + l8 * 8 + l7) * HPAD);
                #pragma unroll
                for (int djp = 0; djp < 4; djp++) {
                    uint32_t r4[4];
                    ldsm_x4t(r4, vbase + (rowa + (2 * djp + l16) * 8) * 2u);
                    mma16(o[2 * djp],     pa[kk], r4[0], r4[1]);
                    mma16(o[2 * djp + 1], pa[kk], r4[2], r4[3]);
                }
                mma16(o[8], pa[kk], bone, bone);
            }
        }
    }

    // ---- epilogue: l lives in o[8][0]/o[8][2] of the tig==0 lane ----
    float l0 = __shfl_sync(0xffffffffu, o[8][0], lane & 28);
    float l1 = __shfl_sync(0xffffffffu, o[8][2], lane & 28);
    float i0 = __fdividef(1.f, l0);
    float i1 = __fdividef(1.f, l1);
    const int r0 = s0 + warp * 16 + g;
    #pragma unroll
    for (int dj = 0; dj < 8; dj++) {
        int col = dj * 8 + tig * 2;
        *(uint32_t*)(ctx + base + (size_t)r0 * EMBED + col) =
            packh2(o[dj][0] * i0, o[dj][1] * i0);
        *(uint32_t*)(ctx + base + (size_t)(r0 + 8) * EMBED + col) =
            packh2(o[dj][2] * i1, o[dj][3] * i1);
    }
}

// ===========================================================================
extern "C" void kernel_launch(void* const* d_in, const int* in_sizes, int n_in,
                              void* d_out, int out_size)
{
    const float* query = (const float*)d_in[0];
    const float* key   = (const float*)d_in[1];
    const float* value = (const float*)d_in[2];
    const float* Wq    = (const float*)d_in[3];
    const float* bq    = (const float*)d_in[4];
    const float* Wk    = (const float*)d_in[5];
    const float* bk    = (const float*)d_in[6];
    const float* Wv    = (const float*)d_in[7];
    const float* bv    = (const float*)d_in[8];
    const float* Wo    = (const float*)d_in[9];
    const float* bo    = (const float*)d_in[10];
    float* out = (float*)d_out;

    const int M = in_sizes[0] / EMBED;   // 4096
    const int B = 2;
    const int S = M / B;                 // 2048

    __half *xq, *xk, *xv, *wh, *qh, *kh, *vh, *ch;
    cudaGetSymbolAddress((void**)&xq, g_xq);
    cudaGetSymbolAddress((void**)&xk, g_xk);
    cudaGetSymbolAddress((void**)&xv, g_xv);
    cudaGetSymbolAddress((void**)&wh, g_wh);
    cudaGetSymbolAddress((void**)&qh, g_qh);
    cudaGetSymbolAddress((void**)&kh, g_kh);
    cudaGetSymbolAddress((void**)&vh, g_vh);
    cudaGetSymbolAddress((void**)&ch, g_ch);

    cudaFuncSetAttribute(gemm_p,
                         cudaFuncAttributeMaxDynamicSharedMemorySize, G_SMEM_BYTES);
    cudaFuncSetAttribute(flash_tc,
                         cudaFuncAttributeMaxDynamicSharedMemorySize, FLASH_SMEM);

    // 1) fp32 -> fp16 conversion of inputs and weights (one launch).
    cvt7<<<dim3(NELEM / 4096, 7), 256>>>(
        query, key, value, Wq, Wk, Wv, Wo,
        xq, xk, xv, wh, wh + WELEM, wh + 2 * WELEM, wh + 3 * WELEM,
        NELEM, WELEM);

    // 2) Q/K/V projections -> fp16 (persistent: 296 CTAs over 768 tiles).
    gemm_p<<<296, 256, G_SMEM_BYTES>>>(xq, xk, xv,
                                       wh, wh + WELEM, wh + 2 * WELEM,
                                       bq, bk, bv,
                                       nullptr, qh, kh, vh,
                                       EMBED, EMBED, 768, 1);

    // 3) flash attention -> ctx (fp16).
    dim3 agrid(S / 128, NHEADS, B);
    flash_tc<<<agrid, 256, FLASH_SMEM>>>(qh, kh, vh, ch, S);

    // 4) output projection -> out (fp32; 256 tiles, 1 per CTA).
    gemm_p<<<256, 256, G_SMEM_BYTES>>>(ch, ch, ch,
                                       wh + 3 * WELEM, wh + 3 * WELEM, wh + 3 * WELEM,
                                       bo, bo, bo,
                                       out, nullptr, nullptr, nullptr,
                                       EMBED, EMBED, 256, 0);
}

// round 16
// speedup vs baseline: 1.0585x; 1.0585x over previous
#include <cuda_runtime.h>
#include <cuda_fp16.h>
#include <cstdint>
#include <math.h>

#define EMBED   1024
#define NHEADS  16
#define MAXROWS 4096                    // B*S
#define NELEM   (MAXROWS * EMBED)       // 4M
#define WELEM   (EMBED * EMBED)         // 1M
#define QSCALE  0.18033688011112042f    // (1/8) * log2(e)

// Scratch (no cudaMalloc allowed).
__device__ __half g_xq[NELEM];          // fp16 query input
__device__ __half g_xk[NELEM];          // fp16 key input
__device__ __half g_xv[NELEM];          // fp16 value input
__device__ __half g_wh[4 * WELEM];      // fp16 Wq|Wk|Wv|Wo
__device__ __half g_qh[NELEM];          // fp16 q (scaled by QSCALE)
__device__ __half g_kh[NELEM];          // fp16 k
__device__ __half g_vh[NELEM];          // fp16 v
__device__ __half g_ch[NELEM];          // fp16 ctx

// ============================ helpers ======================================
__device__ __forceinline__ uint32_t smem_u32(const void* p) {
    uint32_t a;
    asm("{ .reg .u64 t; cvta.to.shared.u64 t, %1; cvt.u32.u64 %0, t; }"
        : "=r"(a) : "l"(p));
    return a;
}
__device__ __forceinline__ uint32_t packh2(float lo, float hi) {
    __half2 h = __floats2half2_rn(lo, hi);
    return *(uint32_t*)&h;
}
__device__ __forceinline__ float ex2f(float x) {   // MUFU 2^x (fp32)
    float y;
    asm("ex2.approx.f32 %0, %1;" : "=f"(y) : "f"(x));
    return y;
}
__device__ __forceinline__ uint32_t hexp2x2(uint32_t x) {  // MUFU 2^x on half2
    uint32_t y;
    asm("ex2.approx.f16x2 %0, %1;" : "=r"(y) : "r"(x));
    return y;
}

#define CPA(dst, src) \
    asm volatile("cp.async.cg.shared.global [%0], [%1], 16;" :: "r"(dst), "l"(src) : "memory")
#define CP_COMMIT() asm volatile("cp.async.commit_group;" ::: "memory")
#define CP_WAIT1()  asm volatile("cp.async.wait_group 1;" ::: "memory")
#define CP_WAIT0()  asm volatile("cp.async.wait_group 0;" ::: "memory")

// m16n8k16 fp16 MMA, fp32 accumulate in place.
__device__ __forceinline__ void mma16(float* d, const uint32_t* a, uint32_t b0, uint32_t b1) {
    asm volatile(
        "mma.sync.aligned.m16n8k16.row.col.f32.f16.f16.f32 "
        "{%0,%1,%2,%3},{%4,%5,%6,%7},{%8,%9},{%0,%1,%2,%3};"
        : "+f"(d[0]), "+f"(d[1]), "+f"(d[2]), "+f"(d[3])
        : "r"(a[0]), "r"(a[1]), "r"(a[2]), "r"(a[3]), "r"(b0), "r"(b1));
}
__device__ __forceinline__ void ldsm_x4(uint32_t* r, uint32_t addr) {
    asm volatile("ldmatrix.sync.aligned.m8n8.x4.shared.b16 {%0,%1,%2,%3}, [%4];"
                 : "=r"(r[0]), "=r"(r[1]), "=r"(r[2]), "=r"(r[3]) : "r"(addr));
}
__device__ __forceinline__ void ldsm_x4t(uint32_t* r, uint32_t addr) {
    asm volatile("ldmatrix.sync.aligned.m8n8.x4.trans.shared.b16 {%0,%1,%2,%3}, [%4];"
                 : "=r"(r[0]), "=r"(r[1]), "=r"(r[2]), "=r"(r[3]) : "r"(addr));
}

// ===========================================================================
// Prep: fp32 -> fp16, 16 elements/thread. blockIdx.y selects one of 7 tensors.
// ===========================================================================
__global__ __launch_bounds__(256) void cvt7(
    const float* __restrict__ s0, const float* __restrict__ s1,
    const float* __restrict__ s2, const float* __restrict__ s3,
    const float* __restrict__ s4, const float* __restrict__ s5,
    const float* __restrict__ s6,
    __half* __restrict__ d0, __half* __restrict__ d1, __half* __restrict__ d2,
    __half* __restrict__ d3, __half* __restrict__ d4, __half* __restrict__ d5,
    __half* __restrict__ d6, int n_big, int n_small)
{
    const int z = blockIdx.y;
    const float* s; __half* d; int n;
    switch (z) {
        case 0: s = s0; d = d0; n = n_big;   break;
        case 1: s = s1; d = d1; n = n_big;   break;
        case 2: s = s2; d = d2; n = n_big;   break;
        case 3: s = s3; d = d3; n = n_small; break;
        case 4: s = s4; d = d4; n = n_small; break;
        case 5: s = s5; d = d5; n = n_small; break;
        default: s = s6; d = d6; n = n_small; break;
    }
    int i = (blockIdx.x * 256 + threadIdx.x) * 16;
    if (i < n) {
        float4 a = *(const float4*)(s + i);
        float4 b = *(const float4*)(s + i + 4);
        float4 c = *(const float4*)(s + i + 8);
        float4 e = *(const float4*)(s + i + 12);
        uint4 o1, o2;
        o1.x = packh2(a.x, a.y);
        o1.y = packh2(a.z, a.w);
        o1.z = packh2(b.x, b.y);
        o1.w = packh2(b.z, b.w);
        o2.x = packh2(c.x, c.y);
        o2.y = packh2(c.z, c.w);
        o2.z = packh2(e.x, e.y);
        o2.w = packh2(e.z, e.w);
        *(uint4*)(d + i)     = o1;
        *(uint4*)(d + i + 8) = o2;
    }
}

// ===========================================================================
// fp16 tensor-core NT GEMM (validated champion): C = A W^T + bias.
// 128x128 tile, K-chunk 64 halves, 3-stage cp.async ring, 8 warps, m16n8k16.
// ===========================================================================
#define G_SMEM_BYTES 98304   // 3 stages x (A 16KB + W 16KB)

__global__ __launch_bounds__(256, 2) void gemm_h(
    const __half* __restrict__ A0, const __half* __restrict__ A1, const __half* __restrict__ A2,
    const __half* __restrict__ W0, const __half* __restrict__ W1, const __half* __restrict__ W2,
    const float* __restrict__ b0, const float* __restrict__ b1, const float* __restrict__ b2,
    float* __restrict__ Cf, __half* __restrict__ H0, __half* __restrict__ H1,
    __half* __restrict__ H2, int M, int N, int K, int mode)
{
    extern __shared__ __align__(16) char smem[];
    const uint32_t sb = smem_u32(smem);

    const int tid  = threadIdx.x;
    const int lane = tid & 31;
    const int wid  = tid >> 5;
    const int g    = lane >> 2;
    const int tig  = lane & 3;
    const int wm   = wid & 1;
    const int wn   = wid >> 1;
    const int bm   = blockIdx.x * 128;
    const int bn   = blockIdx.y * 128;
    const int z    = blockIdx.z;

    const __half* A    = (z == 0) ? A0 : (z == 1) ? A1 : A2;
    const __half* W    = (z == 0) ? W0 : (z == 1) ? W1 : W2;
    const float*  bias = (z == 0) ? b0 : (z == 1) ? b1 : b2;

    const int lrow = tid >> 3;      // 0..31
    const int lc8  = tid & 7;       // 16B chunk 0..7

    float acc[4][4][4];
    #pragma unroll
    for (int mt = 0; mt < 4; mt++)
        #pragma unroll
        for (int nt = 0; nt < 4; nt++)
            #pragma unroll
            for (int r = 0; r < 4; r++) acc[mt][nt][r] = 0.f;

    const int NCH = K >> 6;         // 16 chunks of 64 halves

    auto issue = [&](int c, int st) {
        const int k0 = c * 64;
        #pragma unroll
        for (int p = 0; p < 4; p++) {
            int r = lrow + p * 32;
            uint32_t dA = sb + st * 32768u + (uint32_t)(r * 128 + ((lc8 ^ (r & 7)) << 4));
            CPA(dA,          A + (size_t)(bm + r) * K + k0 + lc8 * 8);
            CPA(dA + 16384u, W + (size_t)(bn + r) * K + k0 + lc8 * 8);
        }
    };

    issue(0, 0); CP_COMMIT();
    issue(1, 1); CP_COMMIT();

    const int l7  = lane & 7;
    const int l8  = (lane >> 3) & 1;
    const int l16 = lane >> 4;

    int st_c  = 0;
    int st_n2 = 2;

    for (int c = 0; c < NCH; c++) {
        if (c + 1 < NCH) CP_WAIT1(); else CP_WAIT0();
        __syncthreads();
        if (c + 2 < NCH) { issue(c + 2, st_n2); CP_COMMIT(); }

        const uint32_t stg = sb + (uint32_t)(st_c * 32768);

        #pragma unroll
        for (int kk = 0; kk < 4; kk++) {
            uint32_t af[4][4], bf[4][2];
            #pragma unroll
            for (int mt = 0; mt < 4; mt++) {
                int row = wm * 64 + mt * 16 + l8 * 8 + l7;
                int c8  = kk * 2 + l16;
                ldsm_x4(af[mt], stg + (uint32_t)(row * 128 + ((c8 ^ (row & 7)) << 4)));
            }
            #pragma unroll
            for (int ntp = 0; ntp < 2; ntp++) {
                int row = wn * 32 + ntp * 16 + l16 * 8 + l7;
                int c8  = kk * 2 + l8;
                uint32_t r4[4];
                ldsm_x4(r4, stg + 16384u + (uint32_t)(row * 128 + ((c8 ^ (row & 7)) << 4)));
                bf[2 * ntp][0]     = r4[0];
                bf[2 * ntp][1]     = r4[1];
                bf[2 * ntp + 1][0] = r4[2];
                bf[2 * ntp + 1][1] = r4[3];
            }
            #pragma unroll
            for (int mt = 0; mt < 4; mt++)
                #pragma unroll
                for (int nt = 0; nt < 4; nt++)
                    mma16(acc[mt][nt], af[mt], bf[nt][0], bf[nt][1]);
        }
        st_c  = (st_c  == 2) ? 0 : st_c + 1;
        st_n2 = (st_n2 == 2) ? 0 : st_n2 + 1;
    }

    if (mode == 1) {
        __half* H = (z == 0) ? H0 : (z == 1) ? H1 : H2;
        const float sc = (z == 0) ? QSCALE : 1.f;
        #pragma unroll
        for (int nt = 0; nt < 4; nt++) {
            int col = bn + wn * 32 + nt * 8 + tig * 2;
            float2 bv = *(const float2*)(bias + col);
            #pragma unroll
            for (int mt = 0; mt < 4; mt++) {
                int r0 = bm + wm * 64 + mt * 16 + g;
                *(uint32_t*)(H + (size_t)r0 * N + col) =
                    packh2((acc[mt][nt][0] + bv.x) * sc, (acc[mt][nt][1] + bv.y) * sc);
                *(uint32_t*)(H + (size_t)(r0 + 8) * N + col) =
                    packh2((acc[mt][nt][2] + bv.x) * sc, (acc[mt][nt][3] + bv.y) * sc);
            }
        }
    } else {
        #pragma unroll
        for (int nt = 0; nt < 4; nt++) {
            int col = bn + wn * 32 + nt * 8 + tig * 2;
            float2 bv = *(const float2*)(bias + col);
            #pragma unroll
            for (int mt = 0; mt < 4; mt++) {
                int r0 = bm + wm * 64 + mt * 16 + g;
                *(float2*)(Cf + (size_t)r0 * N + col) =
                    make_float2(acc[mt][nt][0] + bv.x, acc[mt][nt][1] + bv.y);
                *(float2*)(Cf + (size_t)(r0 + 8) * N + col) =
                    make_float2(acc[mt][nt][2] + bv.x, acc[mt][nt][3] + bv.y);
            }
        }
    }
}

// ===========================================================================
// fp16 tensor-core flash attention — champion configuration:
// fp32-acc QK, packed fp16 MUFU exp into P A-frags, 4-stage K/V ring in tile
// pairs (one barrier / 2 tiles), constant ones-column B-frag row-sum,
// vote-skipped O rescale.
// ===========================================================================
#define HPAD 72
#define OFF_Q  0
#define KV_STG (2 * 64 * HPAD)                   // halves per K+V stage
#define OFF_K(s) (128 * HPAD + (s) * KV_STG)
#define OFF_V(s) (OFF_K(s) + 64 * HPAD)
#define FLASH_SMEM ((128 * HPAD + 4 * KV_STG) * 2)   // 92160 B

__global__ __launch_bounds__(256, 2) void flash_tc(
    const __half* __restrict__ Qh, const __half* __restrict__ Kh,
    const __half* __restrict__ Vh, __half* __restrict__ ctx, int S)
{
    extern __shared__ __half smh[];
    const uint32_t sb = smem_u32(smh);

    const int tid  = threadIdx.x;
    const int lane = tid & 31;
    const int warp = tid >> 5;
    const int g    = lane >> 2;
    const int tig  = lane & 3;
    const int s0   = blockIdx.x * 128;
    const int h    = blockIdx.y;
    const int b    = blockIdx.z;
    const size_t base = ((size_t)b * S) * EMBED + (size_t)h * 64;

    const int frow = tid >> 3;
    const int fc8  = tid & 7;

    auto issueKV = [&](int c0, int st) {
        const uint32_t kOff = (uint32_t)OFF_K(st);
        const uint32_t vOff = (uint32_t)OFF_V(st);
        #pragma unroll
        for (int i = 0; i < 2; i++) {
            int row = frow + i * 32;
            uint32_t d = (uint32_t)(row * HPAD + fc8 * 8) * 2u;
            const size_t src = base + (size_t)(c0 + row) * EMBED + fc8 * 8;
            CPA(sb + kOff * 2u + d, Kh + src);
            CPA(sb + vOff * 2u + d, Vh + src);
        }
    };
    auto issuePair = [&](int p, int slot) {
        issueKV(p * 128,      slot * 2);
        issueKV(p * 128 + 64, slot * 2 + 1);
    };

    // Prologue: Q + pair 0 as one cp.async group.
    #pragma unroll
    for (int i = 0; i < 4; i++) {
        int row = frow + i * 32;
        CPA(sb + (uint32_t)(OFF_Q + row * HPAD + fc8 * 8) * 2u,
            Qh + base + (size_t)(s0 + row) * EMBED + fc8 * 8);
    }
    issuePair(0, 0);
    CP_COMMIT();

    CP_WAIT0();
    __syncthreads();

    const int l7  = lane & 7;
    const int l8  = (lane >> 3) & 1;
    const int l16 = lane >> 4;

    // Q A-fragments (persist in registers).
    uint32_t qa[4][4];
    {
        int qr = warp * 16 + l8 * 8 + l7;
        #pragma unroll
        for (int kk = 0; kk < 4; kk++)
            ldsm_x4(qa[kk], sb + (uint32_t)((OFF_Q + qr * HPAD + kk * 16 + l16 * 8) * 2));
    }

    // Constant B-fragment for the ones-column row-sum mma.
    const uint32_t bone = (lane < 4) ? 0x3C003C00u : 0u;

    float o[9][4] = {};   // o[8] = row-sum accumulator
    float m0 = -1e30f, m1 = -1e30f;

    const int NP = S >> 7;   // 16 tile-pairs
    for (int p = 0; p < NP; p++) {
        if (p > 0) {
            CP_WAIT0();
            __syncthreads();
        }
        if (p + 1 < NP) { issuePair(p + 1, (p + 1) & 1); CP_COMMIT(); }

        #pragma unroll
        for (int u = 0; u < 2; u++) {
            const int st = (p & 1) * 2 + u;
            const uint32_t kbase = sb + (uint32_t)(OFF_K(st) * 2);
            const uint32_t vbase = sb + (uint32_t)(OFF_V(st) * 2);

            // ---- S = Q' K^T (log2-units) ----
            float c[8][4];
            #pragma unroll
            for (int j = 0; j < 8; j++)
                #pragma unroll
                for (int r = 0; r < 4; r++) c[j][r] = 0.f;

            #pragma unroll
            for (int kk = 0; kk < 4; kk++) {
                #pragma unroll
                for (int jp = 0; jp < 4; jp++) {
                    uint32_t r4[4];
                    uint32_t addr = kbase + (uint32_t)((((2 * jp + l16) * 8 + l7) * HPAD
                                     + kk * 16 + l8 * 8) * 2);
                    ldsm_x4(r4, addr);
                    mma16(c[2 * jp],     qa[kk], r4[0], r4[1]);
                    mma16(c[2 * jp + 1], qa[kk], r4[2], r4[3]);
                }
            }

            // ---- online softmax (rows g and g+8) ----
            float mx0 = -1e30f, mx1 = -1e30f;
            #pragma unroll
            for (int j = 0; j < 8; j++) {
                mx0 = fmaxf(mx0, fmaxf(c[j][0], c[j][1]));
                mx1 = fmaxf(mx1, fmaxf(c[j][2], c[j][3]));
            }
            mx0 = fmaxf(mx0, __shfl_xor_sync(0xffffffffu, mx0, 1));
            mx0 = fmaxf(mx0, __shfl_xor_sync(0xffffffffu, mx0, 2));
            mx1 = fmaxf(mx1, __shfl_xor_sync(0xffffffffu, mx1, 1));
            mx1 = fmaxf(mx1, __shfl_xor_sync(0xffffffffu, mx1, 2));

            bool grew = (mx0 > m0) || (mx1 > m1);
            float mn0 = fmaxf(m0, mx0), mn1 = fmaxf(m1, mx1);
            if (__any_sync(0xffffffffu, grew)) {
                float a0 = ex2f(m0 - mn0), a1 = ex2f(m1 - mn1);
                #pragma unroll
                for (int dj = 0; dj < 9; dj++) {
                    o[dj][0] *= a0; o[dj][1] *= a0;
                    o[dj][2] *= a1; o[dj][3] *= a1;
                }
            }
            m0 = mn0; m1 = mn1;

            // P fragments: packed fp16 exp straight into A-frag layout.
            uint32_t pa[4][4];
            #pragma unroll
            for (int kk = 0; kk < 4; kk++) {
                pa[kk][0] = hexp2x2(packh2(c[2 * kk][0] - mn0,     c[2 * kk][1] - mn0));
                pa[kk][1] = hexp2x2(packh2(c[2 * kk][2] - mn1,     c[2 * kk][3] - mn1));
                pa[kk][2] = hexp2x2(packh2(c[2 * kk + 1][0] - mn0, c[2 * kk + 1][1] - mn0));
                pa[kk][3] = hexp2x2(packh2(c[2 * kk + 1][2] - mn1, c[2 * kk + 1][3] - mn1));
            }

            // ---- O += P V (o[8] = row sums via constant ones-column) ----
            #pragma unroll
            for (int kk = 0; kk < 4; kk++) {
                uint32_t rowa = (uint32_t)((kk * 16 + l8 * 8 + l7) * HPAD);
                #pragma unroll
                for (int djp = 0; djp < 4; djp++) {
                    uint32_t r4[4];
                    ldsm_x4t(r4, vbase + (rowa + (2 * djp + l16) * 8) * 2u);
                    mma16(o[2 * djp],     pa[kk], r4[0], r4[1]);
                    mma16(o[2 * djp + 1], pa[kk], r4[2], r4[3]);
                }
                mma16(o[8], pa[kk], bone, bone);
            }
        }
    }

    // ---- epilogue: l lives in o[8][0]/o[8][2] of the tig==0 lane ----
    float l0 = __shfl_sync(0xffffffffu, o[8][0], lane & 28);
    float l1 = __shfl_sync(0xffffffffu, o[8][2], lane & 28);
    float i0 = __fdividef(1.f, l0);
    float i1 = __fdividef(1.f, l1);
    const int r0 = s0 + warp * 16 + g;
    #pragma unroll
    for (int dj = 0; dj < 8; dj++) {
        int col = dj * 8 + tig * 2;
        *(uint32_t*)(ctx + base + (size_t)r0 * EMBED + col) =
            packh2(o[dj][0] * i0, o[dj][1] * i0);
        *(uint32_t*)(ctx + base + (size_t)(r0 + 8) * EMBED + col) =
            packh2(o[dj][2] * i1, o[dj][3] * i1);
    }
}

// ===========================================================================
extern "C" void kernel_launch(void* const* d_in, const int* in_sizes, int n_in,
                              void* d_out, int out_size)
{
    const float* query = (const float*)d_in[0];
    const float* key   = (const float*)d_in[1];
    const float* value = (const float*)d_in[2];
    const float* Wq    = (const float*)d_in[3];
    const float* bq    = (const float*)d_in[4];
    const float* Wk    = (const float*)d_in[5];
    const float* bk    = (const float*)d_in[6];
    const float* Wv    = (const float*)d_in[7];
    const float* bv    = (const float*)d_in[8];
    const float* Wo    = (const float*)d_in[9];
    const float* bo    = (const float*)d_in[10];
    float* out = (float*)d_out;

    const int M = in_sizes[0] / EMBED;   // 4096
    const int B = 2;
    const int S = M / B;                 // 2048

    __half *xq, *xk, *xv, *wh, *qh, *kh, *vh, *ch;
    cudaGetSymbolAddress((void**)&xq, g_xq);
    cudaGetSymbolAddress((void**)&xk, g_xk);
    cudaGetSymbolAddress((void**)&xv, g_xv);
    cudaGetSymbolAddress((void**)&wh, g_wh);
    cudaGetSymbolAddress((void**)&qh, g_qh);
    cudaGetSymbolAddress((void**)&kh, g_kh);
    cudaGetSymbolAddress((void**)&vh, g_vh);
    cudaGetSymbolAddress((void**)&ch, g_ch);

    cudaFuncSetAttribute(gemm_h,
                         cudaFuncAttributeMaxDynamicSharedMemorySize, G_SMEM_BYTES);
    cudaFuncSetAttribute(flash_tc,
                         cudaFuncAttributeMaxDynamicSharedMemorySize, FLASH_SMEM);

    // 1) fp32 -> fp16 conversion of inputs and weights (one launch).
    cvt7<<<dim3(NELEM / 4096, 7), 256>>>(
        query, key, value, Wq, Wk, Wv, Wo,
        xq, xk, xv, wh, wh + WELEM, wh + 2 * WELEM, wh + 3 * WELEM,
        NELEM, WELEM);

    // 2) Q/K/V projections -> fp16 (q pre-scaled by QSCALE).
    dim3 g3(M / 128, EMBED / 128, 3);
    gemm_h<<<g3, 256, G_SMEM_BYTES>>>(xq, xk, xv,
                                      wh, wh + WELEM, wh + 2 * WELEM,
                                      bq, bk, bv,
                                      nullptr, qh, kh, vh,
                                      M, EMBED, EMBED, 1);

    // 3) flash attention -> ctx (fp16).
    dim3 agrid(S / 128, NHEADS, B);
    flash_tc<<<agrid, 256, FLASH_SMEM>>>(qh, kh, vh, ch, S);

    // 4) output projection -> out (fp32).
    dim3 g1(M / 128, EMBED / 128, 1);
    gemm_h<<<g1, 256, G_SMEM_BYTES>>>(ch, ch, ch,
                                      wh + 3 * WELEM, wh + 3 * WELEM, wh + 3 * WELEM,
                                      bo, bo, bo,
                                      out, nullptr, nullptr, nullptr,
                                      M, EMBED, EMBED, 0);
}

// round 17
// speedup vs baseline: 1.1722x; 1.1074x over previous
#include <cuda_runtime.h>
#include <cuda_fp16.h>
#include <cstdint>
#include <math.h>

#define EMBED   1024
#define NHEADS  16
#define MAXROWS 4096                    // B*S
#define NELEM   (MAXROWS * EMBED)       // 4M
#define WELEM   (EMBED * EMBED)         // 1M
#define QSCALE  0.18033688011112042f    // (1/8) * log2(e)

// Scratch (no cudaMalloc allowed).
__device__ __half g_xq[NELEM];          // fp16 query input
__device__ __half g_xk[NELEM];          // fp16 key input
__device__ __half g_xv[NELEM];          // fp16 value input
__device__ __half g_wh[4 * WELEM];      // fp16 Wq|Wk|Wv|Wo
__device__ __half g_qh[NELEM];          // fp16 q (scaled by QSCALE)
__device__ __half g_kh[NELEM];          // fp16 k
__device__ __half g_vh[NELEM];          // fp16 v
__device__ __half g_ch[NELEM];          // fp16 ctx

// ============================ helpers ======================================
__device__ __forceinline__ uint32_t smem_u32(const void* p) {
    uint32_t a;
    asm("{ .reg .u64 t; cvta.to.shared.u64 t, %1; cvt.u32.u64 %0, t; }"
        : "=r"(a) : "l"(p));
    return a;
}
__device__ __forceinline__ uint32_t packh2(float lo, float hi) {
    __half2 h = __floats2half2_rn(lo, hi);
    return *(uint32_t*)&h;
}
__device__ __forceinline__ float ex2f(float x) {   // MUFU 2^x (fp32)
    float y;
    asm("ex2.approx.f32 %0, %1;" : "=f"(y) : "f"(x));
    return y;
}
__device__ __forceinline__ uint32_t hexp2x2(uint32_t x) {  // MUFU 2^x on half2
    uint32_t y;
    asm("ex2.approx.f16x2 %0, %1;" : "=r"(y) : "r"(x));
    return y;
}

#define CPA(dst, src) \
    asm volatile("cp.async.cg.shared.global [%0], [%1], 16;" :: "r"(dst), "l"(src) : "memory")
#define CP_COMMIT() asm volatile("cp.async.commit_group;" ::: "memory")
#define CP_WAIT1()  asm volatile("cp.async.wait_group 1;" ::: "memory")
#define CP_WAIT0()  asm volatile("cp.async.wait_group 0;" ::: "memory")

// m16n8k16 fp16 MMA, fp32 accumulate in place.
__device__ __forceinline__ void mma16(float* d, const uint32_t* a, uint32_t b0, uint32_t b1) {
    asm volatile(
        "mma.sync.aligned.m16n8k16.row.col.f32.f16.f16.f32 "
        "{%0,%1,%2,%3},{%4,%5,%6,%7},{%8,%9},{%0,%1,%2,%3};"
        : "+f"(d[0]), "+f"(d[1]), "+f"(d[2]), "+f"(d[3])
        : "r"(a[0]), "r"(a[1]), "r"(a[2]), "r"(a[3]), "r"(b0), "r"(b1));
}
__device__ __forceinline__ void ldsm_x4(uint32_t* r, uint32_t addr) {
    asm volatile("ldmatrix.sync.aligned.m8n8.x4.shared.b16 {%0,%1,%2,%3}, [%4];"
                 : "=r"(r[0]), "=r"(r[1]), "=r"(r[2]), "=r"(r[3]) : "r"(addr));
}
__device__ __forceinline__ void ldsm_x4t(uint32_t* r, uint32_t addr) {
    asm volatile("ldmatrix.sync.aligned.m8n8.x4.trans.shared.b16 {%0,%1,%2,%3}, [%4];"
                 : "=r"(r[0]), "=r"(r[1]), "=r"(r[2]), "=r"(r[3]) : "r"(addr));
}

// ===========================================================================
// Prep: fp32 -> fp16, 16 elements/thread. blockIdx.y selects one of 7 tensors.
// ===========================================================================
__global__ __launch_bounds__(256) void cvt7(
    const float* __restrict__ s0, const float* __restrict__ s1,
    const float* __restrict__ s2, const float* __restrict__ s3,
    const float* __restrict__ s4, const float* __restrict__ s5,
    const float* __restrict__ s6,
    __half* __restrict__ d0, __half* __restrict__ d1, __half* __restrict__ d2,
    __half* __restrict__ d3, __half* __restrict__ d4, __half* __restrict__ d5,
    __half* __restrict__ d6, int n_big, int n_small)
{
    const int z = blockIdx.y;
    const float* s; __half* d; int n;
    switch (z) {
        case 0: s = s0; d = d0; n = n_big;   break;
        case 1: s = s1; d = d1; n = n_big;   break;
        case 2: s = s2; d = d2; n = n_big;   break;
        case 3: s = s3; d = d3; n = n_small; break;
        case 4: s = s4; d = d4; n = n_small; break;
        case 5: s = s5; d = d5; n = n_small; break;
        default: s = s6; d = d6; n = n_small; break;
    }
    int i = (blockIdx.x * 256 + threadIdx.x) * 16;
    if (i < n) {
        float4 a = *(const float4*)(s + i);
        float4 b = *(const float4*)(s + i + 4);
        float4 c = *(const float4*)(s + i + 8);
        float4 e = *(const float4*)(s + i + 12);
        uint4 o1, o2;
        o1.x = packh2(a.x, a.y);
        o1.y = packh2(a.z, a.w);
        o1.z = packh2(b.x, b.y);
        o1.w = packh2(b.z, b.w);
        o2.x = packh2(c.x, c.y);
        o2.y = packh2(c.z, c.w);
        o2.z = packh2(e.x, e.y);
        o2.w = packh2(e.z, e.w);
        *(uint4*)(d + i)     = o1;
        *(uint4*)(d + i + 8) = o2;
    }
}

// ===========================================================================
// fp16 tensor-core NT GEMM (validated champion + constant row offset bm0):
// C = A W^T + bias. 128x128 tile, K-chunk 64 halves, 3-stage cp.async ring,
// 8 warps, m16n8k16.
// ===========================================================================
#define G_SMEM_BYTES 98304   // 3 stages x (A 16KB + W 16KB)

__global__ __launch_bounds__(256, 2) void gemm_h(
    const __half* __restrict__ A0, const __half* __restrict__ A1, const __half* __restrict__ A2,
    const __half* __restrict__ W0, const __half* __restrict__ W1, const __half* __restrict__ W2,
    const float* __restrict__ b0, const float* __restrict__ b1, const float* __restrict__ b2,
    float* __restrict__ Cf, __half* __restrict__ H0, __half* __restrict__ H1,
    __half* __restrict__ H2, int bm0, int N, int K, int mode)
{
    extern __shared__ __align__(16) char smem[];
    const uint32_t sb = smem_u32(smem);

    const int tid  = threadIdx.x;
    const int lane = tid & 31;
    const int wid  = tid >> 5;
    const int g    = lane >> 2;
    const int tig  = lane & 3;
    const int wm   = wid & 1;
    const int wn   = wid >> 1;
    const int bm   = bm0 + blockIdx.x * 128;
    const int bn   = blockIdx.y * 128;
    const int z    = blockIdx.z;

    const __half* A    = (z == 0) ? A0 : (z == 1) ? A1 : A2;
    const __half* W    = (z == 0) ? W0 : (z == 1) ? W1 : W2;
    const float*  bias = (z == 0) ? b0 : (z == 1) ? b1 : b2;

    const int lrow = tid >> 3;      // 0..31
    const int lc8  = tid & 7;       // 16B chunk 0..7

    float acc[4][4][4];
    #pragma unroll
    for (int mt = 0; mt < 4; mt++)
        #pragma unroll
        for (int nt = 0; nt < 4; nt++)
            #pragma unroll
            for (int r = 0; r < 4; r++) acc[mt][nt][r] = 0.f;

    const int NCH = K >> 6;         // 16 chunks of 64 halves

    auto issue = [&](int c, int st) {
        const int k0 = c * 64;
        #pragma unroll
        for (int p = 0; p < 4; p++) {
            int r = lrow + p * 32;
            uint32_t dA = sb + st * 32768u + (uint32_t)(r * 128 + ((lc8 ^ (r & 7)) << 4));
            CPA(dA,          A + (size_t)(bm + r) * K + k0 + lc8 * 8);
            CPA(dA + 16384u, W + (size_t)(bn + r) * K + k0 + lc8 * 8);
        }
    };

    issue(0, 0); CP_COMMIT();
    issue(1, 1); CP_COMMIT();

    const int l7  = lane & 7;
    const int l8  = (lane >> 3) & 1;
    const int l16 = lane >> 4;

    int st_c  = 0;
    int st_n2 = 2;

    for (int c = 0; c < NCH; c++) {
        if (c + 1 < NCH) CP_WAIT1(); else CP_WAIT0();
        __syncthreads();
        if (c + 2 < NCH) { issue(c + 2, st_n2); CP_COMMIT(); }

        const uint32_t stg = sb + (uint32_t)(st_c * 32768);

        #pragma unroll
        for (int kk = 0; kk < 4; kk++) {
            uint32_t af[4][4], bf[4][2];
            #pragma unroll
            for (int mt = 0; mt < 4; mt++) {
                int row = wm * 64 + mt * 16 + l8 * 8 + l7;
                int c8  = kk * 2 + l16;
                ldsm_x4(af[mt], stg + (uint32_t)(row * 128 + ((c8 ^ (row & 7)) << 4)));
            }
            #pragma unroll
            for (int ntp = 0; ntp < 2; ntp++) {
                int row = wn * 32 + ntp * 16 + l16 * 8 + l7;
                int c8  = kk * 2 + l8;
                uint32_t r4[4];
                ldsm_x4(r4, stg + 16384u + (uint32_t)(row * 128 + ((c8 ^ (row & 7)) << 4)));
                bf[2 * ntp][0]     = r4[0];
                bf[2 * ntp][1]     = r4[1];
                bf[2 * ntp + 1][0] = r4[2];
                bf[2 * ntp + 1][1] = r4[3];
            }
            #pragma unroll
            for (int mt = 0; mt < 4; mt++)
                #pragma unroll
                for (int nt = 0; nt < 4; nt++)
                    mma16(acc[mt][nt], af[mt], bf[nt][0], bf[nt][1]);
        }
        st_c  = (st_c  == 2) ? 0 : st_c + 1;
        st_n2 = (st_n2 == 2) ? 0 : st_n2 + 1;
    }

    if (mode == 1) {
        __half* H = (z == 0) ? H0 : (z == 1) ? H1 : H2;
        const float sc = (z == 0) ? QSCALE : 1.f;
        #pragma unroll
        for (int nt = 0; nt < 4; nt++) {
            int col = bn + wn * 32 + nt * 8 + tig * 2;
            float2 bv = *(const float2*)(bias + col);
            #pragma unroll
            for (int mt = 0; mt < 4; mt++) {
                int r0 = bm + wm * 64 + mt * 16 + g;
                *(uint32_t*)(H + (size_t)r0 * N + col) =
                    packh2((acc[mt][nt][0] + bv.x) * sc, (acc[mt][nt][1] + bv.y) * sc);
                *(uint32_t*)(H + (size_t)(r0 + 8) * N + col) =
                    packh2((acc[mt][nt][2] + bv.x) * sc, (acc[mt][nt][3] + bv.y) * sc);
            }
        }
    } else {
        #pragma unroll
        for (int nt = 0; nt < 4; nt++) {
            int col = bn + wn * 32 + nt * 8 + tig * 2;
            float2 bv = *(const float2*)(bias + col);
            #pragma unroll
            for (int mt = 0; mt < 4; mt++) {
                int r0 = bm + wm * 64 + mt * 16 + g;
                *(float2*)(Cf + (size_t)r0 * N + col) =
                    make_float2(acc[mt][nt][0] + bv.x, acc[mt][nt][1] + bv.y);
                *(float2*)(Cf + (size_t)(r0 + 8) * N + col) =
                    make_float2(acc[mt][nt][2] + bv.x, acc[mt][nt][3] + bv.y);
            }
        }
    }
}

// ===========================================================================
// fp16 tensor-core flash attention — champion configuration, batch given by
// the constant bfix (grid z = 1).
// ===========================================================================
#define HPAD 72
#define OFF_Q  0
#define KV_STG (2 * 64 * HPAD)                   // halves per K+V stage
#define OFF_K(s) (128 * HPAD + (s) * KV_STG)
#define OFF_V(s) (OFF_K(s) + 64 * HPAD)
#define FLASH_SMEM ((128 * HPAD + 4 * KV_STG) * 2)   // 92160 B

__global__ __launch_bounds__(256, 2) void flash_tc(
    const __half* __restrict__ Qh, const __half* __restrict__ Kh,
    const __half* __restrict__ Vh, __half* __restrict__ ctx, int S, int bfix)
{
    extern __shared__ __half smh[];
    const uint32_t sb = smem_u32(smh);

    const int tid  = threadIdx.x;
    const int lane = tid & 31;
    const int warp = tid >> 5;
    const int g    = lane >> 2;
    const int tig  = lane & 3;
    const int s0   = blockIdx.x * 128;
    const int h    = blockIdx.y;
    const int b    = bfix;
    const size_t base = ((size_t)b * S) * EMBED + (size_t)h * 64;

    const int frow = tid >> 3;
    const int fc8  = tid & 7;

    auto issueKV = [&](int c0, int st) {
        const uint32_t kOff = (uint32_t)OFF_K(st);
        const uint32_t vOff = (uint32_t)OFF_V(st);
        #pragma unroll
        for (int i = 0; i < 2; i++) {
            int row = frow + i * 32;
            uint32_t d = (uint32_t)(row * HPAD + fc8 * 8) * 2u;
            const size_t src = base + (size_t)(c0 + row) * EMBED + fc8 * 8;
            CPA(sb + kOff * 2u + d, Kh + src);
            CPA(sb + vOff * 2u + d, Vh + src);
        }
    };
    auto issuePair = [&](int p, int slot) {
        issueKV(p * 128,      slot * 2);
        issueKV(p * 128 + 64, slot * 2 + 1);
    };

    // Prologue: Q + pair 0 as one cp.async group.
    #pragma unroll
    for (int i = 0; i < 4; i++) {
        int row = frow + i * 32;
        CPA(sb + (uint32_t)(OFF_Q + row * HPAD + fc8 * 8) * 2u,
            Qh + base + (size_t)(s0 + row) * EMBED + fc8 * 8);
    }
    issuePair(0, 0);
    CP_COMMIT();

    CP_WAIT0();
    __syncthreads();

    const int l7  = lane & 7;
    const int l8  = (lane >> 3) & 1;
    const int l16 = lane >> 4;

    // Q A-fragments (persist in registers).
    uint32_t qa[4][4];
    {
        int qr = warp * 16 + l8 * 8 + l7;
        #pragma unroll
        for (int kk = 0; kk < 4; kk++)
            ldsm_x4(qa[kk], sb + (uint32_t)((OFF_Q + qr * HPAD + kk * 16 + l16 * 8) * 2));
    }

    // Constant B-fragment for the ones-column row-sum mma.
    const uint32_t bone = (lane < 4) ? 0x3C003C00u : 0u;

    float o[9][4] = {};   // o[8] = row-sum accumulator
    float m0 = -1e30f, m1 = -1e30f;

    const int NP = S >> 7;   // 16 tile-pairs
    for (int p = 0; p < NP; p++) {
        if (p > 0) {
            CP_WAIT0();
            __syncthreads();
        }
        if (p + 1 < NP) { issuePair(p + 1, (p + 1) & 1); CP_COMMIT(); }

        #pragma unroll
        for (int u = 0; u < 2; u++) {
            const int st = (p & 1) * 2 + u;
            const uint32_t kbase = sb + (uint32_t)(OFF_K(st) * 2);
            const uint32_t vbase = sb + (uint32_t)(OFF_V(st) * 2);

            // ---- S = Q' K^T (log2-units) ----
            float c[8][4];
            #pragma unroll
            for (int j = 0; j < 8; j++)
                #pragma unroll
                for (int r = 0; r < 4; r++) c[j][r] = 0.f;

            #pragma unroll
            for (int kk = 0; kk < 4; kk++) {
                #pragma unroll
                for (int jp = 0; jp < 4; jp++) {
                    uint32_t r4[4];
                    uint32_t addr = kbase + (uint32_t)((((2 * jp + l16) * 8 + l7) * HPAD
                                     + kk * 16 + l8 * 8) * 2);
                    ldsm_x4(r4, addr);
                    mma16(c[2 * jp],     qa[kk], r4[0], r4[1]);
                    mma16(c[2 * jp + 1], qa[kk], r4[2], r4[3]);
                }
            }

            // ---- online softmax (rows g and g+8) ----
            float mx0 = -1e30f, mx1 = -1e30f;
            #pragma unroll
            for (int j = 0; j < 8; j++) {
                mx0 = fmaxf(mx0, fmaxf(c[j][0], c[j][1]));
                mx1 = fmaxf(mx1, fmaxf(c[j][2], c[j][3]));
            }
            mx0 = fmaxf(mx0, __shfl_xor_sync(0xffffffffu, mx0, 1));
            mx0 = fmaxf(mx0, __shfl_xor_sync(0xffffffffu, mx0, 2));
            mx1 = fmaxf(mx1, __shfl_xor_sync(0xffffffffu, mx1, 1));
            mx1 = fmaxf(mx1, __shfl_xor_sync(0xffffffffu, mx1, 2));

            bool grew = (mx0 > m0) || (mx1 > m1);
            float mn0 = fmaxf(m0, mx0), mn1 = fmaxf(m1, mx1);
            if (__any_sync(0xffffffffu, grew)) {
                float a0 = ex2f(m0 - mn0), a1 = ex2f(m1 - mn1);
                #pragma unroll
                for (int dj = 0; dj < 9; dj++) {
                    o[dj][0] *= a0; o[dj][1] *= a0;
                    o[dj][2] *= a1; o[dj][3] *= a1;
                }
            }
            m0 = mn0; m1 = mn1;

            // P fragments: packed fp16 exp straight into A-frag layout.
            uint32_t pa[4][4];
            #pragma unroll
            for (int kk = 0; kk < 4; kk++) {
                pa[kk][0] = hexp2x2(packh2(c[2 * kk][0] - mn0,     c[2 * kk][1] - mn0));
                pa[kk][1] = hexp2x2(packh2(c[2 * kk][2] - mn1,     c[2 * kk][3] - mn1));
                pa[kk][2] = hexp2x2(packh2(c[2 * kk + 1][0] - mn0, c[2 * kk + 1][1] - mn0));
                pa[kk][3] = hexp2x2(packh2(c[2 * kk + 1][2] - mn1, c[2 * kk + 1][3] - mn1));
            }

            // ---- O += P V (o[8] = row sums via constant ones-column) ----
            #pragma unroll
            for (int kk = 0; kk < 4; kk++) {
                uint32_t rowa = (uint32_t)((kk * 16 + l8 * 8 + l7) * HPAD);
                #pragma unroll
                for (int djp = 0; djp < 4; djp++) {
                    uint32_t r4[4];
                    ldsm_x4t(r4, vbase + (rowa + (2 * djp + l16) * 8) * 2u);
                    mma16(o[2 * djp],     pa[kk], r4[0], r4[1]);
                    mma16(o[2 * djp + 1], pa[kk], r4[2], r4[3]);
                }
                mma16(o[8], pa[kk], bone, bone);
            }
        }
    }

    // ---- epilogue: l lives in o[8][0]/o[8][2] of the tig==0 lane ----
    float l0 = __shfl_sync(0xffffffffu, o[8][0], lane & 28);
    float l1 = __shfl_sync(0xffffffffu, o[8][2], lane & 28);
    float i0 = __fdividef(1.f, l0);
    float i1 = __fdividef(1.f, l1);
    const int r0 = s0 + warp * 16 + g;
    #pragma unroll
    for (int dj = 0; dj < 8; dj++) {
        int col = dj * 8 + tig * 2;
        *(uint32_t*)(ctx + base + (size_t)r0 * EMBED + col) =
            packh2(o[dj][0] * i0, o[dj][1] * i0);
        *(uint32_t*)(ctx + base + (size_t)(r0 + 8) * EMBED + col) =
            packh2(o[dj][2] * i1, o[dj][3] * i1);
    }
}

// ===========================================================================
extern "C" void kernel_launch(void* const* d_in, const int* in_sizes, int n_in,
                              void* d_out, int out_size)
{
    const float* query = (const float*)d_in[0];
    const float* key   = (const float*)d_in[1];
    const float* value = (const float*)d_in[2];
    const float* Wq    = (const float*)d_in[3];
    const float* bq    = (const float*)d_in[4];
    const float* Wk    = (const float*)d_in[5];
    const float* bk    = (const float*)d_in[6];
    const float* Wv    = (const float*)d_in[7];
    const float* bv    = (const float*)d_in[8];
    const float* Wo    = (const float*)d_in[9];
    const float* bo    = (const float*)d_in[10];
    float* out = (float*)d_out;

    const int M = in_sizes[0] / EMBED;   // 4096
    const int S = M / 2;                 // 2048
    const int HM = M / 2;                // rows per batch

    __half *xq, *xk, *xv, *wh, *qh, *kh, *vh, *ch;
    cudaGetSymbolAddress((void**)&xq, g_xq);
    cudaGetSymbolAddress((void**)&xk, g_xk);
    cudaGetSymbolAddress((void**)&xv, g_xv);
    cudaGetSymbolAddress((void**)&wh, g_wh);
    cudaGetSymbolAddress((void**)&qh, g_qh);
    cudaGetSymbolAddress((void**)&kh, g_kh);
    cudaGetSymbolAddress((void**)&vh, g_vh);
    cudaGetSymbolAddress((void**)&ch, g_ch);

    cudaFuncSetAttribute(gemm_h,
                         cudaFuncAttributeMaxDynamicSharedMemorySize, G_SMEM_BYTES);
    cudaFuncSetAttribute(flash_tc,
                         cudaFuncAttributeMaxDynamicSharedMemorySize, FLASH_SMEM);

    // Fork/join pipeline: chain A (batch 0) on the default stream, chain B
    // (batch 1) on a forked non-blocking stream. Event edges express the
    // only true dependencies; CTAs of independent kernels fill each other's
    // partial waves.
    cudaStream_t s1;
    cudaStreamCreateWithFlags(&s1, cudaStreamNonBlocking);
    cudaEvent_t eC, eB;
    cudaEventCreateWithFlags(&eC, cudaEventDisableTiming);
    cudaEventCreateWithFlags(&eB, cudaEventDisableTiming);

    // 1) fp32 -> fp16 conversion of inputs and weights (one launch).
    cvt7<<<dim3(NELEM / 4096, 7), 256>>>(
        query, key, value, Wq, Wk, Wv, Wo,
        xq, xk, xv, wh, wh + WELEM, wh + 2 * WELEM, wh + 3 * WELEM,
        NELEM, WELEM);
    cudaEventRecord(eC, 0);
    cudaStreamWaitEvent(s1, eC, 0);

    dim3 g3h(HM / 128, EMBED / 128, 3);
    dim3 g1h(HM / 128, EMBED / 128, 1);
    dim3 fgrid(S / 128, NHEADS, 1);

    // 2) Q/K/V projections, batch-split (b0 first for scheduler priority).
    gemm_h<<<g3h, 256, G_SMEM_BYTES, 0>>>(xq, xk, xv,
                                          wh, wh + WELEM, wh + 2 * WELEM,
                                          bq, bk, bv,
                                          nullptr, qh, kh, vh,
                                          0, EMBED, EMBED, 1);
    gemm_h<<<g3h, 256, G_SMEM_BYTES, s1>>>(xq, xk, xv,
                                           wh, wh + WELEM, wh + 2 * WELEM,
                                           bq, bk, bv,
                                           nullptr, qh, kh, vh,
                                           HM, EMBED, EMBED, 1);

    // 3) flash attention per batch.
    flash_tc<<<fgrid, 256, FLASH_SMEM, 0>>>(qh, kh, vh, ch, S, 0);
    flash_tc<<<fgrid, 256, FLASH_SMEM, s1>>>(qh, kh, vh, ch, S, 1);

    // 4) output projection per batch.
    gemm_h<<<g1h, 256, G_SMEM_BYTES, 0>>>(ch, ch, ch,
                                          wh + 3 * WELEM, wh + 3 * WELEM, wh + 3 * WELEM,
                                          bo, bo, bo,
                                          out, nullptr, nullptr, nullptr,
                                          0, EMBED, EMBED, 0);
    gemm_h<<<g1h, 256, G_SMEM_BYTES, s1>>>(ch, ch, ch,
                                           wh + 3 * WELEM, wh + 3 * WELEM, wh + 3 * WELEM,
                                           bo, bo, bo,
                                           out, nullptr, nullptr, nullptr,
                                           HM, EMBED, EMBED, 0);

    // Join chain B back into the main stream.
    cudaEventRecord(eB, s1);
    cudaStreamWaitEvent(0, eB, 0);
}